// round 1
// baseline (speedup 1.0000x reference)
#include <cuda_runtime.h>
#include <math.h>

// Shapes (fixed by the problem)
#define BB 8
#define LL 1024
#define DD 1024
#define HH 16
#define HSZ 64
#define RR 257           // 2*MAXREL+1
#define NBH (BB*HH)      // 128
#define MM (BB*LL)       // 8192

// ---------------- scratch (device globals; no allocation allowed) ----------------
__device__ float g_q[(size_t)NBH*LL*HSZ];            // 32 MB
__device__ float g_k[(size_t)NBH*LL*HSZ];            // 32 MB
__device__ float g_v[(size_t)NBH*LL*HSZ];            // 32 MB
__device__ float g_qrel[(size_t)NBH*LL*RR];          // 33.7 MB : q . embd_k[r]
__device__ float g_w[(size_t)NBH*LL*RR];             // 33.7 MB : sum of probs per rel bucket
__device__ float g_attn[(size_t)NBH*LL*LL];          // 512 MB  : scores / probs
__device__ float g_ctx[(size_t)MM*DD];               // 32 MB   : context pre out-proj

// ---------------- Kernel 1: kqv = x @ W_kqv + b, scatter to head-major q/k/v ----
// M=8192, N=3072, K=1024. BM=BN=128, BK=16, 256 threads, 8x8 per thread.
__global__ __launch_bounds__(256) void k_gemm_kqv(
    const float* __restrict__ A, const float* __restrict__ Bm,
    const float* __restrict__ bias)
{
    const int K = 1024, N = 3072;
    __shared__ float As[16][128];
    __shared__ float Bs[16][128];
    int tid = threadIdx.x;
    int tx = tid & 15, ty = tid >> 4;
    int rowBase = blockIdx.y * 128;
    int colBase = blockIdx.x * 128;

    float acc[8][8];
    #pragma unroll
    for (int i = 0; i < 8; i++)
        #pragma unroll
        for (int j = 0; j < 8; j++) acc[i][j] = 0.f;

    for (int k0 = 0; k0 < K; k0 += 16) {
        #pragma unroll
        for (int f = tid; f < 512; f += 256) {
            int ar = f >> 2, ac4 = (f & 3) << 2;
            float4 v = *(const float4*)&A[(size_t)(rowBase + ar) * K + k0 + ac4];
            As[ac4 + 0][ar] = v.x; As[ac4 + 1][ar] = v.y;
            As[ac4 + 2][ar] = v.z; As[ac4 + 3][ar] = v.w;
        }
        #pragma unroll
        for (int f = tid; f < 512; f += 256) {
            int br = f >> 5, bc4 = (f & 31) << 2;
            *(float4*)&Bs[br][bc4] =
                *(const float4*)&Bm[(size_t)(k0 + br) * N + colBase + bc4];
        }
        __syncthreads();
        #pragma unroll
        for (int kk = 0; kk < 16; kk++) {
            float a[8], b[8];
            *(float4*)&a[0] = *(const float4*)&As[kk][ty * 8];
            *(float4*)&a[4] = *(const float4*)&As[kk][ty * 8 + 4];
            *(float4*)&b[0] = *(const float4*)&Bs[kk][tx * 8];
            *(float4*)&b[4] = *(const float4*)&Bs[kk][tx * 8 + 4];
            #pragma unroll
            for (int i = 0; i < 8; i++)
                #pragma unroll
                for (int j = 0; j < 8; j++) acc[i][j] += a[i] * b[j];
        }
        __syncthreads();
    }

    #pragma unroll
    for (int i = 0; i < 8; i++) {
        int m = rowBase + ty * 8 + i;
        int b = m >> 10, l = m & 1023;
        #pragma unroll
        for (int j = 0; j < 8; j++) {
            int n = colBase + tx * 8 + j;
            float v = acc[i][j] + bias[n];
            int part = n >> 10, rem = n & 1023;
            int h = rem >> 6, hs = rem & 63;
            size_t dst = ((size_t)(b * HH + h) * LL + l) * HSZ + hs;
            if (part == 0)      g_q[dst] = v;
            else if (part == 1) g_k[dst] = v;
            else                g_v[dst] = v;
        }
    }
}

// ---------------- Kernel 2: qrel[bh,l,r] = q[bh,l,:] . embd_k[r,:] ---------------
// Batched [64l x 64r], K=64. 256 threads, 4x4 per thread.
__global__ __launch_bounds__(256) void k_qrel(const float* __restrict__ ek)
{
    __shared__ float qs[64][65];
    __shared__ float es[64][65];
    int bh = blockIdx.z;
    int lt = blockIdx.y * 64;
    int rt = blockIdx.x * 64;
    int tid = threadIdx.x;
    int tx = tid & 15, ty = tid >> 4;

    for (int f = tid; f < 4096; f += 256) {
        int r = f >> 6, c = f & 63;
        qs[r][c] = g_q[((size_t)bh * LL + lt + r) * HSZ + c];
        int rr = rt + r;
        es[r][c] = (rr < RR) ? ek[rr * HSZ + c] : 0.f;
    }
    __syncthreads();

    float acc[4][4];
    #pragma unroll
    for (int i = 0; i < 4; i++)
        #pragma unroll
        for (int j = 0; j < 4; j++) acc[i][j] = 0.f;

    #pragma unroll 8
    for (int d = 0; d < 64; d++) {
        float a[4], e[4];
        #pragma unroll
        for (int i = 0; i < 4; i++) a[i] = qs[ty * 4 + i][d];
        #pragma unroll
        for (int j = 0; j < 4; j++) e[j] = es[tx * 4 + j][d];
        #pragma unroll
        for (int i = 0; i < 4; i++)
            #pragma unroll
            for (int j = 0; j < 4; j++) acc[i][j] += a[i] * e[j];
    }

    #pragma unroll
    for (int i = 0; i < 4; i++) {
        int l = lt + ty * 4 + i;
        #pragma unroll
        for (int j = 0; j < 4; j++) {
            int r = rt + tx * 4 + j;
            if (r < RR) g_qrel[((size_t)bh * LL + l) * RR + r] = acc[i][j];
        }
    }
}

// ---------------- Kernel 3: scores = (q.k^T + qrel[rel]) / 8, mask --------------
__global__ __launch_bounds__(256) void k_scores(const int* __restrict__ mask)
{
    __shared__ float qs[64][65];
    __shared__ float ks[64][65];
    int bh = blockIdx.z;
    int qt = blockIdx.y * 64;
    int kt = blockIdx.x * 64;
    int tid = threadIdx.x;
    int tx = tid & 15, ty = tid >> 4;

    for (int f = tid; f < 4096; f += 256) {
        int r = f >> 6, c = f & 63;
        qs[r][c] = g_q[((size_t)bh * LL + qt + r) * HSZ + c];
        ks[r][c] = g_k[((size_t)bh * LL + kt + r) * HSZ + c];
    }
    __syncthreads();

    float acc[4][4];
    #pragma unroll
    for (int i = 0; i < 4; i++)
        #pragma unroll
        for (int j = 0; j < 4; j++) acc[i][j] = 0.f;

    #pragma unroll 8
    for (int d = 0; d < 64; d++) {
        float a[4], b[4];
        #pragma unroll
        for (int i = 0; i < 4; i++) a[i] = qs[ty * 4 + i][d];
        #pragma unroll
        for (int j = 0; j < 4; j++) b[j] = ks[tx * 4 + j][d];
        #pragma unroll
        for (int i = 0; i < 4; i++)
            #pragma unroll
            for (int j = 0; j < 4; j++) acc[i][j] += a[i] * b[j];
    }

    int bb = bh >> 4;
    int mk[4];
    #pragma unroll
    for (int j = 0; j < 4; j++) mk[j] = mask[bb * LL + kt + tx * 4 + j];

    #pragma unroll
    for (int i = 0; i < 4; i++) {
        int qi = qt + ty * 4 + i;
        const float* qrow = &g_qrel[((size_t)bh * LL + qi) * RR];
        #pragma unroll
        for (int j = 0; j < 4; j++) {
            int kj = kt + tx * 4 + j;
            int dd = kj - qi;
            int ridx = dd < -128 ? 0 : (dd > 128 ? 256 : dd + 128);
            float v = (acc[i][j] + qrow[ridx]) * 0.125f;   // 1/sqrt(64)
            if (mk[j] == 0) v = -INFINITY;
            g_attn[((size_t)bh * LL + qi) * LL + kj] = v;
        }
    }
}

// ---------------- Kernel 4: row softmax + rel-bucket accumulation w[q,r] --------
// One 256-thread block per (bh, q) row of length 1024.
__global__ __launch_bounds__(256) void k_softmax()
{
    int row = blockIdx.x;            // bh*L + q
    int q = row & 1023;
    float* p = &g_attn[(size_t)row * LL];
    int tid = threadIdx.x;
    __shared__ float red[256];
    __shared__ float ws[RR];

    float v[4];
    float mx = -INFINITY;
    #pragma unroll
    for (int s = 0; s < 4; s++) { v[s] = p[tid + (s << 8)]; mx = fmaxf(mx, v[s]); }
    red[tid] = mx; __syncthreads();
    for (int o = 128; o; o >>= 1) {
        if (tid < o) red[tid] = fmaxf(red[tid], red[tid + o]);
        __syncthreads();
    }
    mx = red[0];
    __syncthreads();

    float sum = 0.f;
    #pragma unroll
    for (int s = 0; s < 4; s++) { v[s] = __expf(v[s] - mx); sum += v[s]; }
    red[tid] = sum; __syncthreads();
    for (int o = 128; o; o >>= 1) {
        if (tid < o) red[tid] += red[tid + o];
        __syncthreads();
    }
    float inv = 1.f / red[0];

    ws[tid] = 0.f;
    if (tid == 0) ws[256] = 0.f;
    __syncthreads();

    float l0 = 0.f, l2 = 0.f;
    #pragma unroll
    for (int s = 0; s < 4; s++) {
        int k = tid + (s << 8);
        float pv = v[s] * inv;
        p[k] = pv;
        int dd = k - q;
        if (dd <= -128)      l0 += pv;
        else if (dd >= 128)  l2 += pv;
        else                 atomicAdd(&ws[dd + 128], pv);   // unique r per k: no contention
    }
    #pragma unroll
    for (int o = 16; o; o >>= 1) {
        l0 += __shfl_down_sync(0xffffffffu, l0, o);
        l2 += __shfl_down_sync(0xffffffffu, l2, o);
    }
    if ((tid & 31) == 0) {
        if (l0 != 0.f) atomicAdd(&ws[0], l0);
        if (l2 != 0.f) atomicAdd(&ws[256], l2);
    }
    __syncthreads();

    g_w[(size_t)row * RR + tid] = ws[tid];
    if (tid == 0) g_w[(size_t)row * RR + 256] = ws[256];
}

// ---------------- Kernel 5: ctx = attn@v + w@embd_v, write [B,L,D] layout -------
__global__ __launch_bounds__(256) void k_ctx(const float* __restrict__ ev)
{
    __shared__ float as[64][33];
    __shared__ float vs[32][65];
    int bh = blockIdx.y;
    int qt = blockIdx.x * 64;
    int tid = threadIdx.x;
    int tx = tid & 15, ty = tid >> 4;

    float acc[4][4];
    #pragma unroll
    for (int i = 0; i < 4; i++)
        #pragma unroll
        for (int j = 0; j < 4; j++) acc[i][j] = 0.f;

    // part 1: attn [64 x 1024] @ v [1024 x 64]
    for (int k0 = 0; k0 < LL; k0 += 32) {
        for (int f = tid; f < 2048; f += 256) {
            int r = f >> 5, c = f & 31;
            as[r][c] = g_attn[((size_t)bh * LL + qt + r) * LL + k0 + c];
        }
        for (int f = tid; f < 2048; f += 256) {
            int r = f >> 6, c = f & 63;
            vs[r][c] = g_v[((size_t)bh * LL + k0 + r) * HSZ + c];
        }
        __syncthreads();
        #pragma unroll 8
        for (int kk = 0; kk < 32; kk++) {
            float a[4], b[4];
            #pragma unroll
            for (int i = 0; i < 4; i++) a[i] = as[ty * 4 + i][kk];
            #pragma unroll
            for (int j = 0; j < 4; j++) b[j] = vs[kk][tx * 4 + j];
            #pragma unroll
            for (int i = 0; i < 4; i++)
                #pragma unroll
                for (int j = 0; j < 4; j++) acc[i][j] += a[i] * b[j];
        }
        __syncthreads();
    }

    // part 2: w [64 x 257] @ embd_v [257 x 64]
    for (int r0 = 0; r0 < RR; r0 += 32) {
        for (int f = tid; f < 2048; f += 256) {
            int r = f >> 5, c = f & 31;
            int rr = r0 + c;
            as[r][c] = (rr < RR) ? g_w[((size_t)bh * LL + qt + r) * RR + rr] : 0.f;
        }
        for (int f = tid; f < 2048; f += 256) {
            int r = f >> 6, c = f & 63;
            int rr = r0 + r;
            vs[r][c] = (rr < RR) ? ev[rr * HSZ + c] : 0.f;
        }
        __syncthreads();
        #pragma unroll 8
        for (int kk = 0; kk < 32; kk++) {
            float a[4], b[4];
            #pragma unroll
            for (int i = 0; i < 4; i++) a[i] = as[ty * 4 + i][kk];
            #pragma unroll
            for (int j = 0; j < 4; j++) b[j] = vs[kk][tx * 4 + j];
            #pragma unroll
            for (int i = 0; i < 4; i++)
                #pragma unroll
                for (int j = 0; j < 4; j++) acc[i][j] += a[i] * b[j];
        }
        __syncthreads();
    }

    int bb = bh >> 4, h = bh & 15;
    #pragma unroll
    for (int i = 0; i < 4; i++) {
        int l = qt + ty * 4 + i;
        #pragma unroll
        for (int j = 0; j < 4; j++) {
            int n = tx * 4 + j;
            g_ctx[((size_t)(bb * LL + l)) * DD + h * HSZ + n] = acc[i][j];
        }
    }
}

// ---------------- Kernel 6: out = ctx @ W_o + b_o -------------------------------
__global__ __launch_bounds__(256) void k_gemm_out(
    const float* __restrict__ Wo, const float* __restrict__ bo,
    float* __restrict__ out)
{
    const int K = 1024, N = 1024;
    __shared__ float As[16][128];
    __shared__ float Bs[16][128];
    int tid = threadIdx.x;
    int tx = tid & 15, ty = tid >> 4;
    int rowBase = blockIdx.y * 128;
    int colBase = blockIdx.x * 128;

    float acc[8][8];
    #pragma unroll
    for (int i = 0; i < 8; i++)
        #pragma unroll
        for (int j = 0; j < 8; j++) acc[i][j] = 0.f;

    for (int k0 = 0; k0 < K; k0 += 16) {
        #pragma unroll
        for (int f = tid; f < 512; f += 256) {
            int ar = f >> 2, ac4 = (f & 3) << 2;
            float4 v = *(const float4*)&g_ctx[(size_t)(rowBase + ar) * K + k0 + ac4];
            As[ac4 + 0][ar] = v.x; As[ac4 + 1][ar] = v.y;
            As[ac4 + 2][ar] = v.z; As[ac4 + 3][ar] = v.w;
        }
        #pragma unroll
        for (int f = tid; f < 512; f += 256) {
            int br = f >> 5, bc4 = (f & 31) << 2;
            *(float4*)&Bs[br][bc4] =
                *(const float4*)&Wo[(size_t)(k0 + br) * N + colBase + bc4];
        }
        __syncthreads();
        #pragma unroll
        for (int kk = 0; kk < 16; kk++) {
            float a[8], b[8];
            *(float4*)&a[0] = *(const float4*)&As[kk][ty * 8];
            *(float4*)&a[4] = *(const float4*)&As[kk][ty * 8 + 4];
            *(float4*)&b[0] = *(const float4*)&Bs[kk][tx * 8];
            *(float4*)&b[4] = *(const float4*)&Bs[kk][tx * 8 + 4];
            #pragma unroll
            for (int i = 0; i < 8; i++)
                #pragma unroll
                for (int j = 0; j < 8; j++) acc[i][j] += a[i] * b[j];
        }
        __syncthreads();
    }

    #pragma unroll
    for (int i = 0; i < 8; i++) {
        int m = rowBase + ty * 8 + i;
        #pragma unroll
        for (int j = 0; j < 8; j++) {
            int n = colBase + tx * 8 + j;
            out[(size_t)m * N + n] = acc[i][j] + bo[n];
        }
    }
}

// ---------------- launch --------------------------------------------------------
extern "C" void kernel_launch(void* const* d_in, const int* in_sizes, int n_in,
                              void* d_out, int out_size)
{
    const float* x      = (const float*)d_in[0];
    const float* W_kqv  = (const float*)d_in[1];
    const float* b_kqv  = (const float*)d_in[2];
    const float* W_o    = (const float*)d_in[3];
    const float* b_o    = (const float*)d_in[4];
    const float* embd_k = (const float*)d_in[5];
    const float* embd_v = (const float*)d_in[6];
    const int*   mask   = (const int*)d_in[7];
    float* out = (float*)d_out;

    // 1. kqv projection + head scatter
    k_gemm_kqv<<<dim3(3072 / 128, MM / 128), 256>>>(x, W_kqv, b_kqv);
    // 2. q . embd_k[r] table
    k_qrel<<<dim3((RR + 63) / 64, LL / 64, NBH), 256>>>(embd_k);
    // 3. attention scores (content + relative) + mask
    k_scores<<<dim3(LL / 64, LL / 64, NBH), 256>>>(mask);
    // 4. softmax + rel-bucket weights
    k_softmax<<<NBH * LL, 256>>>();
    // 5. context = attn@v + w@embd_v
    k_ctx<<<dim3(LL / 64, NBH), 256>>>(embd_v);
    // 6. output projection
    k_gemm_out<<<dim3(1024 / 128, MM / 128), 256>>>(W_o, b_o, out);
}

// round 3
// speedup vs baseline: 1.0351x; 1.0351x over previous
#include <cuda_runtime.h>
#include <cuda_bf16.h>
#include <math.h>
#include <stdint.h>

// Shapes (fixed by the problem)
#define BB 8
#define LL 1024
#define DD 1024
#define HH 16
#define HSZ 64
#define RR 257           // 2*MAXREL+1
#define NBH (BB*HH)      // 128
#define MM (BB*LL)       // 8192

// ---------------- scratch (device globals; no allocation allowed) ----------------
__device__ float g_q[(size_t)NBH*LL*HSZ];            // 32 MB
__device__ float g_k[(size_t)NBH*LL*HSZ];            // 32 MB
__device__ float g_v[(size_t)NBH*LL*HSZ];            // 32 MB
__device__ float g_qrel[(size_t)NBH*LL*RR];          // 33.7 MB : q . embd_k[r]
__device__ float g_w[(size_t)NBH*LL*RR];             // 33.7 MB : prob mass per rel bucket
__device__ float g_attn[(size_t)NBH*LL*LL];          // 512 MB  : scores / probs
__device__ float g_ctx[(size_t)MM*DD];               // 32 MB   : context pre out-proj

// ======================= warp-level mma.sync helpers ============================
// mma.sync.aligned.m16n8k16.row.col.f32.bf16.bf16.f32 (baseline PTX, sm_80+).
// Fragment layouts (lane = gid*4+tg, gid=lane>>2 in 0..7, tg=lane&3):
//   A (16x16): a0=(gid, tg*2..+1) a1=(gid+8, tg*2..+1) a2=(gid, tg*2+8..+9) a3=(gid+8, +8..9)
//   B (16x8) : b0=(k=tg*2..+1, n=gid)  b1=(k=tg*2+8..+9, n=gid)
//   C (16x8) : c0=(gid, tg*2) c1=(gid, tg*2+1) c2=(gid+8, tg*2) c3=(gid+8, tg*2+1)
__device__ __forceinline__ void mma_bf16(float c[4], const uint32_t a[4], const uint32_t b[2]) {
    asm volatile(
        "mma.sync.aligned.m16n8k16.row.col.f32.bf16.bf16.f32 "
        "{%0,%1,%2,%3}, {%4,%5,%6,%7}, {%8,%9}, {%0,%1,%2,%3};"
        : "+f"(c[0]), "+f"(c[1]), "+f"(c[2]), "+f"(c[3])
        : "r"(a[0]), "r"(a[1]), "r"(a[2]), "r"(a[3]), "r"(b[0]), "r"(b[1]));
}

#define SK 40   // smem row stride in bf16 elements for BK=32 tiles (pad 8; even -> 4B aligned)

// Load A fragment from smem tile As[m][k] (row stride SK), origin (m0, k0)
__device__ __forceinline__ void ldfragA(uint32_t a[4], const __nv_bfloat16* As,
                                        int m0, int k0, int gid, int tg) {
    const __nv_bfloat16* p = As + (m0 + gid) * SK + k0 + tg * 2;
    a[0] = *(const uint32_t*)p;
    a[1] = *(const uint32_t*)(p + 8 * SK);
    a[2] = *(const uint32_t*)(p + 8);
    a[3] = *(const uint32_t*)(p + 8 * SK + 8);
}
// Load B fragment from smem tile Bs[n][k] (row stride SK), origin (n0, k0)
__device__ __forceinline__ void ldfragB(uint32_t b[2], const __nv_bfloat16* Bs,
                                        int n0, int k0, int gid, int tg) {
    const __nv_bfloat16* p = Bs + (n0 + gid) * SK + k0 + tg * 2;
    b[0] = *(const uint32_t*)p;
    b[1] = *(const uint32_t*)(p + 8);
}

__device__ __forceinline__ void bf_split(float x, __nv_bfloat16& h, __nv_bfloat16& l) {
    h = __float2bfloat16(x);
    l = __float2bfloat16(x - __bfloat162float(h));
}

// ============ Kernel 1/6: dense GEMM 128x128 tile, K=1024, bf16 hi/lo x3 ========
// MODE 0: A = x, scatter +bias to g_q/g_k/g_v (Nw = 3072)
// MODE 1: A = g_ctx, Out = out +bias (Nw = 1024)
template <int MODE>
__global__ __launch_bounds__(256) void mma_gemm(const float* __restrict__ Ain,
                                                const float* __restrict__ W,
                                                const float* __restrict__ bias,
                                                float* __restrict__ Out, int Nw)
{
    __shared__ __nv_bfloat16 Ah[128 * SK], Al[128 * SK], Bh[128 * SK], Bl[128 * SK];
    const int tid = threadIdx.x;
    const int warp = tid >> 5, lane = tid & 31;
    const int gid = lane >> 2, tg = lane & 3;
    const int wm = (warp >> 2) * 64;     // 2 warps in m
    const int wn = (warp & 3) * 32;      // 4 warps in n
    const int rowBase = blockIdx.y * 128;
    const int colBase = blockIdx.x * 128;
    const float* A = (MODE == 0) ? Ain : g_ctx;

    float acc[4][4][4];
    #pragma unroll
    for (int i = 0; i < 4; i++)
        #pragma unroll
        for (int j = 0; j < 4; j++)
            #pragma unroll
            for (int t = 0; t < 4; t++) acc[i][j][t] = 0.f;

    for (int k0 = 0; k0 < 1024; k0 += 32) {
        // A tile [128m x 32k] fp32 -> hi/lo bf16
        #pragma unroll
        for (int i = 0; i < 4; i++) {
            int f = tid + i * 256;
            int m = f >> 3, kq = (f & 7) << 2;
            float4 v = *(const float4*)&A[(size_t)(rowBase + m) * 1024 + k0 + kq];
            __nv_bfloat16 h, l;
            bf_split(v.x, h, l); Ah[m * SK + kq + 0] = h; Al[m * SK + kq + 0] = l;
            bf_split(v.y, h, l); Ah[m * SK + kq + 1] = h; Al[m * SK + kq + 1] = l;
            bf_split(v.z, h, l); Ah[m * SK + kq + 2] = h; Al[m * SK + kq + 2] = l;
            bf_split(v.w, h, l); Ah[m * SK + kq + 3] = h; Al[m * SK + kq + 3] = l;
        }
        // B tile: W[k][n] -> transposed smem Bs[n][k]
        #pragma unroll
        for (int i = 0; i < 4; i++) {
            int f = tid + i * 256;
            int kr = f >> 5, n4 = (f & 31) << 2;
            float4 v = *(const float4*)&W[(size_t)(k0 + kr) * Nw + colBase + n4];
            __nv_bfloat16 h, l;
            bf_split(v.x, h, l); Bh[(n4 + 0) * SK + kr] = h; Bl[(n4 + 0) * SK + kr] = l;
            bf_split(v.y, h, l); Bh[(n4 + 1) * SK + kr] = h; Bl[(n4 + 1) * SK + kr] = l;
            bf_split(v.z, h, l); Bh[(n4 + 2) * SK + kr] = h; Bl[(n4 + 2) * SK + kr] = l;
            bf_split(v.w, h, l); Bh[(n4 + 3) * SK + kr] = h; Bl[(n4 + 3) * SK + kr] = l;
        }
        __syncthreads();

        #pragma unroll
        for (int ks = 0; ks < 2; ks++) {
            int k = ks * 16;
            uint32_t fb_h[4][2], fb_l[4][2], fa[4][4];
            #pragma unroll
            for (int nf = 0; nf < 4; nf++) {
                ldfragB(fb_h[nf], Bh, wn + nf * 8, k, gid, tg);
                ldfragB(fb_l[nf], Bl, wn + nf * 8, k, gid, tg);
            }
            #pragma unroll
            for (int mf = 0; mf < 4; mf++) ldfragA(fa[mf], Ah, wm + mf * 16, k, gid, tg);
            #pragma unroll
            for (int mf = 0; mf < 4; mf++)
                #pragma unroll
                for (int nf = 0; nf < 4; nf++) {
                    mma_bf16(acc[mf][nf], fa[mf], fb_h[nf]);
                    mma_bf16(acc[mf][nf], fa[mf], fb_l[nf]);
                }
            #pragma unroll
            for (int mf = 0; mf < 4; mf++) ldfragA(fa[mf], Al, wm + mf * 16, k, gid, tg);
            #pragma unroll
            for (int mf = 0; mf < 4; mf++)
                #pragma unroll
                for (int nf = 0; nf < 4; nf++)
                    mma_bf16(acc[mf][nf], fa[mf], fb_h[nf]);
        }
        __syncthreads();
    }

    // epilogue
    #pragma unroll
    for (int mf = 0; mf < 4; mf++)
        #pragma unroll
        for (int nf = 0; nf < 4; nf++)
            #pragma unroll
            for (int t = 0; t < 4; t++) {
                int m = wm + mf * 16 + gid + (t >> 1) * 8;
                int n = colBase + wn + nf * 8 + tg * 2 + (t & 1);
                float v = acc[mf][nf][t] + bias[n];
                if (MODE == 0) {
                    int gm = rowBase + m;
                    int b = gm >> 10, l = gm & 1023;
                    int part = n >> 10, rem = n & 1023;
                    int h = rem >> 6, hs = rem & 63;
                    size_t dst = ((size_t)(b * HH + h) * LL + l) * HSZ + hs;
                    if (part == 0)      g_q[dst] = v;
                    else if (part == 1) g_k[dst] = v;
                    else                g_v[dst] = v;
                } else {
                    Out[(size_t)(rowBase + m) * 1024 + n] = v;
                }
            }
}

// ============ Kernel 2: qrel[bh,l,r] = q . embd_k[r]  (mma, K=64) ===============
__global__ __launch_bounds__(256) void k_qrel(const float* __restrict__ ek)
{
    __shared__ __nv_bfloat16 Ah[128 * SK], Al[128 * SK], Bh[128 * SK], Bl[128 * SK];
    const int tid = threadIdx.x;
    const int warp = tid >> 5, lane = tid & 31;
    const int gid = lane >> 2, tg = lane & 3;
    const int wm = (warp >> 2) * 64, wn = (warp & 3) * 32;
    const int bh = blockIdx.z;
    const int lt = blockIdx.y * 128;
    const int rt = blockIdx.x * 128;

    float acc[4][4][4];
    #pragma unroll
    for (int i = 0; i < 4; i++)
        #pragma unroll
        for (int j = 0; j < 4; j++)
            #pragma unroll
            for (int t = 0; t < 4; t++) acc[i][j][t] = 0.f;

    for (int k0 = 0; k0 < 64; k0 += 32) {
        #pragma unroll
        for (int i = 0; i < 4; i++) {
            int f = tid + i * 256;
            int m = f >> 3, kq = (f & 7) << 2;
            float4 v = *(const float4*)&g_q[((size_t)bh * LL + lt + m) * HSZ + k0 + kq];
            __nv_bfloat16 h, l;
            bf_split(v.x, h, l); Ah[m * SK + kq + 0] = h; Al[m * SK + kq + 0] = l;
            bf_split(v.y, h, l); Ah[m * SK + kq + 1] = h; Al[m * SK + kq + 1] = l;
            bf_split(v.z, h, l); Ah[m * SK + kq + 2] = h; Al[m * SK + kq + 2] = l;
            bf_split(v.w, h, l); Bh[0] = Bh[0];  // no-op placeholder removed below
            Ah[m * SK + kq + 3] = h; Al[m * SK + kq + 3] = l;
        }
        #pragma unroll
        for (int i = 0; i < 4; i++) {
            int f = tid + i * 256;
            int n = f >> 3, kq = (f & 7) << 2;
            int r = rt + n;
            float4 v = (r < RR) ? *(const float4*)&ek[r * HSZ + k0 + kq]
                                : make_float4(0.f, 0.f, 0.f, 0.f);
            __nv_bfloat16 h, l;
            bf_split(v.x, h, l); Bh[n * SK + kq + 0] = h; Bl[n * SK + kq + 0] = l;
            bf_split(v.y, h, l); Bh[n * SK + kq + 1] = h; Bl[n * SK + kq + 1] = l;
            bf_split(v.z, h, l); Bh[n * SK + kq + 2] = h; Bl[n * SK + kq + 2] = l;
            bf_split(v.w, h, l); Bh[n * SK + kq + 3] = h; Bl[n * SK + kq + 3] = l;
        }
        __syncthreads();
        #pragma unroll
        for (int ks = 0; ks < 2; ks++) {
            int k = ks * 16;
            uint32_t fb_h[4][2], fb_l[4][2], fa[4][4];
            #pragma unroll
            for (int nf = 0; nf < 4; nf++) {
                ldfragB(fb_h[nf], Bh, wn + nf * 8, k, gid, tg);
                ldfragB(fb_l[nf], Bl, wn + nf * 8, k, gid, tg);
            }
            #pragma unroll
            for (int mf = 0; mf < 4; mf++) ldfragA(fa[mf], Ah, wm + mf * 16, k, gid, tg);
            #pragma unroll
            for (int mf = 0; mf < 4; mf++)
                #pragma unroll
                for (int nf = 0; nf < 4; nf++) {
                    mma_bf16(acc[mf][nf], fa[mf], fb_h[nf]);
                    mma_bf16(acc[mf][nf], fa[mf], fb_l[nf]);
                }
            #pragma unroll
            for (int mf = 0; mf < 4; mf++) ldfragA(fa[mf], Al, wm + mf * 16, k, gid, tg);
            #pragma unroll
            for (int mf = 0; mf < 4; mf++)
                #pragma unroll
                for (int nf = 0; nf < 4; nf++)
                    mma_bf16(acc[mf][nf], fa[mf], fb_h[nf]);
        }
        __syncthreads();
    }

    #pragma unroll
    for (int mf = 0; mf < 4; mf++)
        #pragma unroll
        for (int nf = 0; nf < 4; nf++)
            #pragma unroll
            for (int t = 0; t < 4; t++) {
                int l = lt + wm + mf * 16 + gid + (t >> 1) * 8;
                int r = rt + wn + nf * 8 + tg * 2 + (t & 1);
                if (r < RR)
                    g_qrel[((size_t)bh * LL + l) * RR + r] = acc[mf][nf][t];
            }
}

// ============ Kernel 3: scores = (q.k^T + qrel[rel]) / 8, mask  (mma) ===========
__global__ __launch_bounds__(256) void k_scores(const int* __restrict__ mask)
{
    __shared__ __nv_bfloat16 Ah[128 * SK], Al[128 * SK], Bh[128 * SK], Bl[128 * SK];
    const int tid = threadIdx.x;
    const int warp = tid >> 5, lane = tid & 31;
    const int gid = lane >> 2, tg = lane & 3;
    const int wm = (warp >> 2) * 64, wn = (warp & 3) * 32;
    const int bh = blockIdx.z;
    const int qt = blockIdx.y * 128;
    const int kt = blockIdx.x * 128;

    float acc[4][4][4];
    #pragma unroll
    for (int i = 0; i < 4; i++)
        #pragma unroll
        for (int j = 0; j < 4; j++)
            #pragma unroll
            for (int t = 0; t < 4; t++) acc[i][j][t] = 0.f;

    for (int k0 = 0; k0 < 64; k0 += 32) {
        #pragma unroll
        for (int i = 0; i < 4; i++) {
            int f = tid + i * 256;
            int m = f >> 3, kq = (f & 7) << 2;
            float4 v = *(const float4*)&g_q[((size_t)bh * LL + qt + m) * HSZ + k0 + kq];
            __nv_bfloat16 h, l;
            bf_split(v.x, h, l); Ah[m * SK + kq + 0] = h; Al[m * SK + kq + 0] = l;
            bf_split(v.y, h, l); Ah[m * SK + kq + 1] = h; Al[m * SK + kq + 1] = l;
            bf_split(v.z, h, l); Ah[m * SK + kq + 2] = h; Al[m * SK + kq + 2] = l;
            bf_split(v.w, h, l); Ah[m * SK + kq + 3] = h; Al[m * SK + kq + 3] = l;
        }
        #pragma unroll
        for (int i = 0; i < 4; i++) {
            int f = tid + i * 256;
            int n = f >> 3, kq = (f & 7) << 2;
            float4 v = *(const float4*)&g_k[((size_t)bh * LL + kt + n) * HSZ + k0 + kq];
            __nv_bfloat16 h, l;
            bf_split(v.x, h, l); Bh[n * SK + kq + 0] = h; Bl[n * SK + kq + 0] = l;
            bf_split(v.y, h, l); Bh[n * SK + kq + 1] = h; Bl[n * SK + kq + 1] = l;
            bf_split(v.z, h, l); Bh[n * SK + kq + 2] = h; Bl[n * SK + kq + 2] = l;
            bf_split(v.w, h, l); Bh[n * SK + kq + 3] = h; Bl[n * SK + kq + 3] = l;
        }
        __syncthreads();
        #pragma unroll
        for (int ks = 0; ks < 2; ks++) {
            int k = ks * 16;
            uint32_t fb_h[4][2], fb_l[4][2], fa[4][4];
            #pragma unroll
            for (int nf = 0; nf < 4; nf++) {
                ldfragB(fb_h[nf], Bh, wn + nf * 8, k, gid, tg);
                ldfragB(fb_l[nf], Bl, wn + nf * 8, k, gid, tg);
            }
            #pragma unroll
            for (int mf = 0; mf < 4; mf++) ldfragA(fa[mf], Ah, wm + mf * 16, k, gid, tg);
            #pragma unroll
            for (int mf = 0; mf < 4; mf++)
                #pragma unroll
                for (int nf = 0; nf < 4; nf++) {
                    mma_bf16(acc[mf][nf], fa[mf], fb_h[nf]);
                    mma_bf16(acc[mf][nf], fa[mf], fb_l[nf]);
                }
            #pragma unroll
            for (int mf = 0; mf < 4; mf++) ldfragA(fa[mf], Al, wm + mf * 16, k, gid, tg);
            #pragma unroll
            for (int mf = 0; mf < 4; mf++)
                #pragma unroll
                for (int nf = 0; nf < 4; nf++)
                    mma_bf16(acc[mf][nf], fa[mf], fb_h[nf]);
        }
        __syncthreads();
    }

    const int bb = bh >> 4;
    #pragma unroll
    for (int mf = 0; mf < 4; mf++)
        #pragma unroll
        for (int nf = 0; nf < 4; nf++)
            #pragma unroll
            for (int t = 0; t < 4; t++) {
                int qi = qt + wm + mf * 16 + gid + (t >> 1) * 8;
                int kj = kt + wn + nf * 8 + tg * 2 + (t & 1);
                int dd = kj - qi;
                int ridx = dd < -128 ? 0 : (dd > 128 ? 256 : dd + 128);
                float v = (acc[mf][nf][t] + g_qrel[((size_t)bh * LL + qi) * RR + ridx]) * 0.125f;
                if (mask[bb * LL + kj] == 0) v = -INFINITY;
                g_attn[((size_t)bh * LL + qi) * LL + kj] = v;
            }
}

// ============ Kernel 4: row softmax + rel-bucket weights ========================
__global__ __launch_bounds__(256) void k_softmax()
{
    int row = blockIdx.x;            // bh*L + q
    int q = row & 1023;
    float* p = &g_attn[(size_t)row * LL];
    int tid = threadIdx.x;
    int wid = tid >> 5, lane = tid & 31;
    __shared__ float red[8];
    __shared__ float ws[RR];

    float v[4];
    float mx = -INFINITY;
    #pragma unroll
    for (int s = 0; s < 4; s++) { v[s] = p[tid + (s << 8)]; mx = fmaxf(mx, v[s]); }
    #pragma unroll
    for (int o = 16; o; o >>= 1) mx = fmaxf(mx, __shfl_xor_sync(0xffffffffu, mx, o));
    if (lane == 0) red[wid] = mx;
    __syncthreads();
    mx = red[0];
    #pragma unroll
    for (int i = 1; i < 8; i++) mx = fmaxf(mx, red[i]);
    __syncthreads();

    float sum = 0.f;
    #pragma unroll
    for (int s = 0; s < 4; s++) { v[s] = __expf(v[s] - mx); sum += v[s]; }
    #pragma unroll
    for (int o = 16; o; o >>= 1) sum += __shfl_xor_sync(0xffffffffu, sum, o);
    if (lane == 0) red[wid] = sum;
    __syncthreads();
    sum = 0.f;
    #pragma unroll
    for (int i = 0; i < 8; i++) sum += red[i];
    float inv = 1.f / sum;

    ws[tid] = 0.f;
    if (tid == 0) ws[256] = 0.f;
    __syncthreads();

    float l0 = 0.f, l2 = 0.f;
    #pragma unroll
    for (int s = 0; s < 4; s++) {
        int k = tid + (s << 8);
        float pv = v[s] * inv;
        p[k] = pv;
        int dd = k - q;
        if (dd <= -128)      l0 += pv;
        else if (dd >= 128)  l2 += pv;
        else                 ws[dd + 128] = pv;        // bijection per row: no atomics
    }
    #pragma unroll
    for (int o = 16; o; o >>= 1) {
        l0 += __shfl_down_sync(0xffffffffu, l0, o);
        l2 += __shfl_down_sync(0xffffffffu, l2, o);
    }
    if (lane == 0) {
        if (l0 != 0.f) atomicAdd(&ws[0], l0);
        if (l2 != 0.f) atomicAdd(&ws[256], l2);
    }
    __syncthreads();

    g_w[(size_t)row * RR + tid] = ws[tid];
    if (tid == 0) g_w[(size_t)row * RR + 256] = ws[256];
}

// ============ Kernel 5: ctx = attn@v + w@embd_v  (mma) ==========================
// BM=128(q), BN=64(hs). 8 warps: 4 in m x 2 in n, each 32x32 (mf 0..1, nf 0..3).
__global__ __launch_bounds__(256) void k_ctx(const float* __restrict__ ev)
{
    __shared__ __nv_bfloat16 Ah[128 * SK], Al[128 * SK], Bh[64 * SK], Bl[64 * SK];
    const int tid = threadIdx.x;
    const int warp = tid >> 5, lane = tid & 31;
    const int gid = lane >> 2, tg = lane & 3;
    const int wm = (warp >> 1) * 32, wn = (warp & 1) * 32;
    const int bh = blockIdx.y;
    const int qt = blockIdx.x * 128;

    float acc[2][4][4];
    #pragma unroll
    for (int i = 0; i < 2; i++)
        #pragma unroll
        for (int j = 0; j < 4; j++)
            #pragma unroll
            for (int t = 0; t < 4; t++) acc[i][j][t] = 0.f;

    // 41 iterations: 32 over attn/v (k=0..1023), 9 over rel buckets (r=0..287, guarded)
    for (int it = 0; it < 41; it++) {
        if (it < 32) {
            int k0 = it * 32;
            // A = attn [128 x 32]
            #pragma unroll
            for (int i = 0; i < 4; i++) {
                int f = tid + i * 256;
                int m = f >> 3, kq = (f & 7) << 2;
                float4 v = *(const float4*)&g_attn[((size_t)bh * LL + qt + m) * LL + k0 + kq];
                __nv_bfloat16 h, l;
                bf_split(v.x, h, l); Ah[m * SK + kq + 0] = h; Al[m * SK + kq + 0] = l;
                bf_split(v.y, h, l); Ah[m * SK + kq + 1] = h; Al[m * SK + kq + 1] = l;
                bf_split(v.z, h, l); Ah[m * SK + kq + 2] = h; Al[m * SK + kq + 2] = l;
                bf_split(v.w, h, l); Ah[m * SK + kq + 3] = h; Al[m * SK + kq + 3] = l;
            }
            // B = v [32k x 64n] -> transposed smem [n][k]
            #pragma unroll
            for (int i = 0; i < 2; i++) {
                int f = tid + i * 256;
                int kr = f >> 4, n4 = (f & 15) << 2;
                float4 v = *(const float4*)&g_v[((size_t)bh * LL + k0 + kr) * HSZ + n4];
                __nv_bfloat16 h, l;
                bf_split(v.x, h, l); Bh[(n4 + 0) * SK + kr] = h; Bl[(n4 + 0) * SK + kr] = l;
                bf_split(v.y, h, l); Bh[(n4 + 1) * SK + kr] = h; Bl[(n4 + 1) * SK + kr] = l;
                bf_split(v.z, h, l); Bh[(n4 + 2) * SK + kr] = h; Bl[(n4 + 2) * SK + kr] = l;
                bf_split(v.w, h, l); Bh[(n4 + 3) * SK + kr] = h; Bl[(n4 + 3) * SK + kr] = l;
            }
        } else {
            int r0 = (it - 32) * 32;
            // A = w [128 x 32 rel buckets], guarded scalar loads (row stride 257)
            #pragma unroll
            for (int i = 0; i < 4; i++) {
                int f = tid + i * 256;
                int m = f >> 3, kq = (f & 7) << 2;
                const float* wrow = &g_w[((size_t)bh * LL + qt + m) * RR];
                #pragma unroll
                for (int j = 0; j < 4; j++) {
                    int r = r0 + kq + j;
                    float x = (r < RR) ? wrow[r] : 0.f;
                    __nv_bfloat16 h, l;
                    bf_split(x, h, l);
                    Ah[m * SK + kq + j] = h; Al[m * SK + kq + j] = l;
                }
            }
            // B = embd_v [32r x 64n] -> transposed
            #pragma unroll
            for (int i = 0; i < 2; i++) {
                int f = tid + i * 256;
                int kr = f >> 4, n4 = (f & 15) << 2;
                int r = r0 + kr;
                float4 v = (r < RR) ? *(const float4*)&ev[r * HSZ + n4]
                                    : make_float4(0.f, 0.f, 0.f, 0.f);
                __nv_bfloat16 h, l;
                bf_split(v.x, h, l); Bh[(n4 + 0) * SK + kr] = h; Bl[(n4 + 0) * SK + kr] = l;
                bf_split(v.y, h, l); Bh[(n4 + 1) * SK + kr] = h; Bl[(n4 + 1) * SK + kr] = l;
                bf_split(v.z, h, l); Bh[(n4 + 2) * SK + kr] = h; Bl[(n4 + 2) * SK + kr] = l;
                bf_split(v.w, h, l); Bh[(n4 + 3) * SK + kr] = h; Bl[(n4 + 3) * SK + kr] = l;
            }
        }
        __syncthreads();
        #pragma unroll
        for (int ks = 0; ks < 2; ks++) {
            int k = ks * 16;
            uint32_t fb_h[4][2], fb_l[4][2], fa[2][4];
            #pragma unroll
            for (int nf = 0; nf < 4; nf++) {
                ldfragB(fb_h[nf], Bh, wn + nf * 8, k, gid, tg);
                ldfragB(fb_l[nf], Bl, wn + nf * 8, k, gid, tg);
            }
            #pragma unroll
            for (int mf = 0; mf < 2; mf++) ldfragA(fa[mf], Ah, wm + mf * 16, k, gid, tg);
            #pragma unroll
            for (int mf = 0; mf < 2; mf++)
                #pragma unroll
                for (int nf = 0; nf < 4; nf++) {
                    mma_bf16(acc[mf][nf], fa[mf], fb_h[nf]);
                    mma_bf16(acc[mf][nf], fa[mf], fb_l[nf]);
                }
            #pragma unroll
            for (int mf = 0; mf < 2; mf++) ldfragA(fa[mf], Al, wm + mf * 16, k, gid, tg);
            #pragma unroll
            for (int mf = 0; mf < 2; mf++)
                #pragma unroll
                for (int nf = 0; nf < 4; nf++)
                    mma_bf16(acc[mf][nf], fa[mf], fb_h[nf]);
        }
        __syncthreads();
    }

    const int bb = bh >> 4, h = bh & 15;
    #pragma unroll
    for (int mf = 0; mf < 2; mf++)
        #pragma unroll
        for (int nf = 0; nf < 4; nf++)
            #pragma unroll
            for (int t = 0; t < 4; t++) {
                int l = qt + wm + mf * 16 + gid + (t >> 1) * 8;
                int n = wn + nf * 8 + tg * 2 + (t & 1);
                g_ctx[((size_t)(bb * LL + l)) * DD + h * HSZ + n] = acc[mf][nf][t];
            }
}

// ---------------- launch --------------------------------------------------------
extern "C" void kernel_launch(void* const* d_in, const int* in_sizes, int n_in,
                              void* d_out, int out_size)
{
    const float* x      = (const float*)d_in[0];
    const float* W_kqv  = (const float*)d_in[1];
    const float* b_kqv  = (const float*)d_in[2];
    const float* W_o    = (const float*)d_in[3];
    const float* b_o    = (const float*)d_in[4];
    const float* embd_k = (const float*)d_in[5];
    const float* embd_v = (const float*)d_in[6];
    const int*   mask   = (const int*)d_in[7];
    float* out = (float*)d_out;

    // 1. kqv projection + head scatter (mma bf16x3)
    mma_gemm<0><<<dim3(3072 / 128, MM / 128), 256>>>(x, W_kqv, b_kqv, nullptr, 3072);
    // 2. q . embd_k[r] table (mma)
    k_qrel<<<dim3(3, LL / 128, NBH), 256>>>(embd_k);
    // 3. attention scores (content + relative) + mask (mma)
    k_scores<<<dim3(LL / 128, LL / 128, NBH), 256>>>(mask);
    // 4. softmax + rel-bucket weights
    k_softmax<<<NBH * LL, 256>>>();
    // 5. context = attn@v + w@embd_v (mma)
    k_ctx<<<dim3(LL / 128, NBH), 256>>>(embd_v);
    // 6. output projection (mma bf16x3)
    mma_gemm<1><<<dim3(1024 / 128, MM / 128), 256>>>(nullptr, W_o, b_o, out, 1024);
}

// round 5
// speedup vs baseline: 1.8238x; 1.7620x over previous
#include <cuda_runtime.h>
#include <cuda_bf16.h>
#include <math.h>
#include <stdint.h>

// Shapes (fixed)
#define BB 8
#define LL 1024
#define DD 1024
#define HH 16
#define HSZ 64
#define RR 257
#define RPAD 288          // padded rel-bucket count (9 * 32)
#define NBH (BB*HH)       // 128
#define MM (BB*LL)        // 8192
#define SK 40             // smem row stride (bf16 elems): 80B rows, conflict-free

// ---------------- scratch (device globals) --------------------------------------
__device__ float g_attn[(size_t)NBH*LL*LL];     // 512MB fp32 scores
__device__ float g_qrel[(size_t)NBH*LL*RR];     // fp32 qrel gather table

__device__ __nv_bfloat16 s_xh[(size_t)MM*DD],   s_xl[(size_t)MM*DD];
__device__ __nv_bfloat16 s_wkh[(size_t)3072*DD], s_wkl[(size_t)3072*DD]; // W_kqv^T [n][k]
__device__ __nv_bfloat16 s_woh[(size_t)DD*DD],  s_wol[(size_t)DD*DD];    // W_o^T
__device__ __nv_bfloat16 s_qh[(size_t)NBH*LL*HSZ], s_ql[(size_t)NBH*LL*HSZ];
__device__ __nv_bfloat16 s_kh[(size_t)NBH*LL*HSZ], s_kl[(size_t)NBH*LL*HSZ];
__device__ __nv_bfloat16 s_vth[(size_t)NBH*HSZ*LL], s_vtl[(size_t)NBH*HSZ*LL]; // v^T [bh][hs][l]
__device__ __nv_bfloat16 s_ekh[(size_t)384*HSZ], s_ekl[(size_t)384*HSZ];       // padded embd_k
__device__ __nv_bfloat16 s_evh[(size_t)HSZ*RPAD], s_evl[(size_t)HSZ*RPAD];     // embd_v^T padded
__device__ __nv_bfloat16 s_ph[(size_t)NBH*LL*LL], s_pl[(size_t)NBH*LL*LL];     // probs hi/lo
__device__ __nv_bfloat16 s_wh[(size_t)NBH*LL*RPAD], s_wl[(size_t)NBH*LL*RPAD]; // bucket mass
__device__ __nv_bfloat16 s_ch[(size_t)MM*DD],   s_cl[(size_t)MM*DD];           // ctx hi/lo

// ======================= PTX helpers ============================================
__device__ __forceinline__ uint32_t smem_cast(const void* p) {
    uint32_t a;
    asm("{ .reg .u64 t; cvta.to.shared.u64 t, %1; cvt.u32.u64 %0, t; }" : "=r"(a) : "l"(p));
    return a;
}
__device__ __forceinline__ void cp16(uint32_t s, const void* g) {
    asm volatile("cp.async.cg.shared.global [%0], [%1], 16;" :: "r"(s), "l"(g));
}
#define CP_COMMIT() asm volatile("cp.async.commit_group;" ::: "memory")
#define CP_WAIT1()  asm volatile("cp.async.wait_group 1;" ::: "memory")
#define CP_WAITALL() asm volatile("cp.async.wait_all;" ::: "memory")

__device__ __forceinline__ void ldmA(uint32_t a[4], uint32_t addr) {
    asm volatile("ldmatrix.sync.aligned.m8n8.x4.shared.b16 {%0,%1,%2,%3}, [%4];"
        : "=r"(a[0]), "=r"(a[1]), "=r"(a[2]), "=r"(a[3]) : "r"(addr));
}
__device__ __forceinline__ void ldmB(uint32_t b[2], uint32_t addr) {
    asm volatile("ldmatrix.sync.aligned.m8n8.x2.shared.b16 {%0,%1}, [%2];"
        : "=r"(b[0]), "=r"(b[1]) : "r"(addr));
}
__device__ __forceinline__ void mma_bf16(float c[4], const uint32_t a[4], const uint32_t b[2]) {
    asm volatile(
        "mma.sync.aligned.m16n8k16.row.col.f32.bf16.bf16.f32 "
        "{%0,%1,%2,%3}, {%4,%5,%6,%7}, {%8,%9}, {%0,%1,%2,%3};"
        : "+f"(c[0]), "+f"(c[1]), "+f"(c[2]), "+f"(c[3])
        : "r"(a[0]), "r"(a[1]), "r"(a[2]), "r"(a[3]), "r"(b[0]), "r"(b[1]));
}
__device__ __forceinline__ void bf_split(float x, __nv_bfloat16& h, __nv_bfloat16& l) {
    h = __float2bfloat16(x);
    l = __float2bfloat16(x - __bfloat162float(h));
}

// smem sizes
#define SZA (128 * SK * 2)            // 10240 B per 128-row tile
#define SZB128 (128 * SK * 2)
#define SZB64  (64 * SK * 2)
#define STG128 (2 * SZA + 2 * SZB128) // 40960 per stage (x3, BN=128)
#define STG64  (2 * SZA + 2 * SZB64)  // 30720 per stage (x3, BN=64)

// --- fill one stage: A (128 rows) + B (BN rows), hi+lo, 16B cp.async ------------
template<int BN>
__device__ __forceinline__ void fill_x3(
    uint32_t aH, uint32_t aL, uint32_t bH, uint32_t bL,
    const __nv_bfloat16* __restrict__ gAh, const __nv_bfloat16* __restrict__ gAl, int sA,
    const __nv_bfloat16* __restrict__ gBh, const __nv_bfloat16* __restrict__ gBl, int sB,
    int kA, int kB, int tid)
{
    #pragma unroll
    for (int i = 0; i < 2; i++) {
        int f = tid + i * 256;
        int row = f >> 2, seg = (f & 3) << 3;
        size_t go = (size_t)row * sA + kA + seg;
        uint32_t so = (uint32_t)((row * SK + seg) * 2);
        cp16(aH + so, gAh + go);
        cp16(aL + so, gAl + go);
    }
    #pragma unroll
    for (int i = 0; i < (BN >> 6); i++) {
        int f = tid + i * 256;
        int row = f >> 2, seg = (f & 3) << 3;
        size_t go = (size_t)row * sB + kB + seg;
        uint32_t so = (uint32_t)((row * SK + seg) * 2);
        cp16(bH + so, gBh + go);
        cp16(bL + so, gBl + go);
    }
}

// --- compute one stage: x3 (AhBh + AhBl + AlBh), NF=4 ---------------------------
template<int MF>
__device__ __forceinline__ void stage_mma(float (*acc)[4][4],
    uint32_t aH, uint32_t aL, uint32_t bH, uint32_t bL, int wm, int wn, int lane)
{
    const int rA = lane & 15, cA = (lane >> 4) << 3;
    const int t16 = lane & 15;
    const int rB = t16 & 7, cB = (t16 >> 3) << 3;
    #pragma unroll
    for (int ks = 0; ks < 2; ks++) {
        const int kb = ks << 4;
        uint32_t fbh[4][2], fbl[4][2], fa[MF][4];
        #pragma unroll
        for (int nf = 0; nf < 4; nf++) {
            uint32_t off = (uint32_t)(((wn + nf * 8 + rB) * SK + kb + cB) * 2);
            ldmB(fbh[nf], bH + off);
            ldmB(fbl[nf], bL + off);
        }
        #pragma unroll
        for (int mf = 0; mf < MF; mf++) {
            uint32_t off = (uint32_t)(((wm + mf * 16 + rA) * SK + kb + cA) * 2);
            ldmA(fa[mf], aH + off);
        }
        #pragma unroll
        for (int mf = 0; mf < MF; mf++)
            #pragma unroll
            for (int nf = 0; nf < 4; nf++) {
                mma_bf16(acc[mf][nf], fa[mf], fbh[nf]);
                mma_bf16(acc[mf][nf], fa[mf], fbl[nf]);
            }
        #pragma unroll
        for (int mf = 0; mf < MF; mf++) {
            uint32_t off = (uint32_t)(((wm + mf * 16 + rA) * SK + kb + cA) * 2);
            ldmA(fa[mf], aL + off);
        }
        #pragma unroll
        for (int mf = 0; mf < MF; mf++)
            #pragma unroll
            for (int nf = 0; nf < 4; nf++)
                mma_bf16(acc[mf][nf], fa[mf], fbh[nf]);
    }
}

// ================= conversion kernels ===========================================
__global__ __launch_bounds__(256) void cvt_x(const float* __restrict__ x)
{
    size_t i = ((size_t)blockIdx.x * 256 + threadIdx.x) * 4;
    float4 v = *(const float4*)(x + i);
    __nv_bfloat16 h0, l0, h1, l1, h2, l2, h3, l3;
    bf_split(v.x, h0, l0); bf_split(v.y, h1, l1);
    bf_split(v.z, h2, l2); bf_split(v.w, h3, l3);
    *(__nv_bfloat162*)(s_xh + i)     = __halves2bfloat162(h0, h1);
    *(__nv_bfloat162*)(s_xh + i + 2) = __halves2bfloat162(h2, h3);
    *(__nv_bfloat162*)(s_xl + i)     = __halves2bfloat162(l0, l1);
    *(__nv_bfloat162*)(s_xl + i + 2) = __halves2bfloat162(l2, l3);
}

// W [1024 x N] -> Wt hi/lo [N x 1024]
__global__ __launch_bounds__(256) void cvt_wT(const float* __restrict__ W, int N)
{
    __shared__ float s[32][33];
    __nv_bfloat16* Th = (N == 3072) ? s_wkh : s_woh;
    __nv_bfloat16* Tl = (N == 3072) ? s_wkl : s_wol;
    int n0 = blockIdx.x * 32, k0 = blockIdx.y * 32;
    int tx = threadIdx.x & 31, ty = threadIdx.x >> 5;
    #pragma unroll
    for (int i = 0; i < 4; i++) {
        int r = ty + i * 8;    // k-local
        s[r][tx] = W[(size_t)(k0 + r) * N + n0 + tx];
    }
    __syncthreads();
    #pragma unroll
    for (int i = 0; i < 4; i++) {
        int r = ty + i * 8;    // n-local
        float v = s[tx][r];    // = W[k0+tx][n0+r]
        __nv_bfloat16 h, l; bf_split(v, h, l);
        size_t d = (size_t)(n0 + r) * DD + k0 + tx;
        Th[d] = h; Tl[d] = l;
    }
}

__global__ __launch_bounds__(256) void cvt_ek(const float* __restrict__ ek)
{
    int i = blockIdx.x * 256 + threadIdx.x;           // 384*64 = 24576
    if (i >= 384 * HSZ) return;
    int r = i >> 6;
    float v = (r < RR) ? ek[r * HSZ + (i & 63)] : 0.f;
    __nv_bfloat16 h, l; bf_split(v, h, l);
    s_ekh[i] = h; s_ekl[i] = l;
}

__global__ __launch_bounds__(256) void cvt_ev(const float* __restrict__ ev)
{
    int i = blockIdx.x * 256 + threadIdx.x;           // 64*288 = 18432
    if (i >= HSZ * RPAD) return;
    int hs = i / RPAD, r = i % RPAD;
    float v = (r < RR) ? ev[r * HSZ + hs] : 0.f;
    __nv_bfloat16 h, l; bf_split(v, h, l);
    s_evh[i] = h; s_evl[i] = l;
}

// ================= GEMM kernels =================================================
// kqv: [8192 x 3072] = x @ W_kqv + bias, scatter to q/k (l-major) and v^T
__global__ __launch_bounds__(256) void k_kqv(const float* __restrict__ bias)
{
    extern __shared__ char sm[];
    const uint32_t sb = smem_cast(sm);
    const int tid = threadIdx.x, warp = tid >> 5, lane = tid & 31;
    const int gid = lane >> 2, tg = lane & 3;
    const int wm = (warp >> 2) * 64, wn = (warp & 3) * 32;
    const int rowBase = blockIdx.y * 128, colBase = blockIdx.x * 128;
    const __nv_bfloat16* gAh = s_xh + (size_t)rowBase * DD;
    const __nv_bfloat16* gAl = s_xl + (size_t)rowBase * DD;
    const __nv_bfloat16* gBh = s_wkh + (size_t)colBase * DD;
    const __nv_bfloat16* gBl = s_wkl + (size_t)colBase * DD;

    float acc[4][4][4];
    #pragma unroll
    for (int i = 0; i < 4; i++) for (int j = 0; j < 4; j++) for (int t = 0; t < 4; t++)
        acc[i][j][t] = 0.f;

    auto fill = [&](int c, int stg) {
        uint32_t aH = sb + stg * STG128, aL = aH + SZA, bH = aL + SZA, bL = bH + SZB128;
        fill_x3<128>(aH, aL, bH, bL, gAh, gAl, DD, gBh, gBl, DD, c * 32, c * 32, tid);
    };
    fill(0, 0); CP_COMMIT();
    fill(1, 1); CP_COMMIT();
    for (int c = 0; c < 32; c++) {
        CP_WAIT1(); __syncthreads();
        int stg = c & 1;
        uint32_t aH = sb + stg * STG128, aL = aH + SZA, bH = aL + SZA, bL = bH + SZB128;
        stage_mma<4>(acc, aH, aL, bH, bL, wm, wn, lane);
        __syncthreads();
        if (c + 2 < 32) fill(c + 2, stg);
        CP_COMMIT();
    }
    CP_WAITALL();

    #pragma unroll
    for (int mf = 0; mf < 4; mf++)
        #pragma unroll
        for (int nf = 0; nf < 4; nf++)
            #pragma unroll
            for (int t = 0; t < 4; t++) {
                int m = wm + mf * 16 + gid + (t >> 1) * 8;
                int n = colBase + wn + nf * 8 + tg * 2 + (t & 1);
                float v = acc[mf][nf][t] + bias[n];
                __nv_bfloat16 h2, l2; bf_split(v, h2, l2);
                int gm = rowBase + m;
                int b = gm >> 10, li = gm & 1023;
                int part = n >> 10, rem = n & 1023, hh = rem >> 6, hs = rem & 63;
                if (part == 0) {
                    size_t d = ((size_t)(b * HH + hh) * LL + li) * HSZ + hs;
                    s_qh[d] = h2; s_ql[d] = l2;
                } else if (part == 1) {
                    size_t d = ((size_t)(b * HH + hh) * LL + li) * HSZ + hs;
                    s_kh[d] = h2; s_kl[d] = l2;
                } else {
                    size_t d = ((size_t)(b * HH + hh) * HSZ + hs) * LL + li;
                    s_vth[d] = h2; s_vtl[d] = l2;
                }
            }
}

// out-proj: out = ctx @ W_o + b_o
__global__ __launch_bounds__(256) void k_out(const float* __restrict__ bias,
                                             float* __restrict__ Out)
{
    extern __shared__ char sm[];
    const uint32_t sb = smem_cast(sm);
    const int tid = threadIdx.x, warp = tid >> 5, lane = tid & 31;
    const int gid = lane >> 2, tg = lane & 3;
    const int wm = (warp >> 2) * 64, wn = (warp & 3) * 32;
    const int rowBase = blockIdx.y * 128, colBase = blockIdx.x * 128;
    const __nv_bfloat16* gAh = s_ch + (size_t)rowBase * DD;
    const __nv_bfloat16* gAl = s_cl + (size_t)rowBase * DD;
    const __nv_bfloat16* gBh = s_woh + (size_t)colBase * DD;
    const __nv_bfloat16* gBl = s_wol + (size_t)colBase * DD;

    float acc[4][4][4];
    #pragma unroll
    for (int i = 0; i < 4; i++) for (int j = 0; j < 4; j++) for (int t = 0; t < 4; t++)
        acc[i][j][t] = 0.f;

    auto fill = [&](int c, int stg) {
        uint32_t aH = sb + stg * STG128, aL = aH + SZA, bH = aL + SZA, bL = bH + SZB128;
        fill_x3<128>(aH, aL, bH, bL, gAh, gAl, DD, gBh, gBl, DD, c * 32, c * 32, tid);
    };
    fill(0, 0); CP_COMMIT();
    fill(1, 1); CP_COMMIT();
    for (int c = 0; c < 32; c++) {
        CP_WAIT1(); __syncthreads();
        int stg = c & 1;
        uint32_t aH = sb + stg * STG128, aL = aH + SZA, bH = aL + SZA, bL = bH + SZB128;
        stage_mma<4>(acc, aH, aL, bH, bL, wm, wn, lane);
        __syncthreads();
        if (c + 2 < 32) fill(c + 2, stg);
        CP_COMMIT();
    }
    CP_WAITALL();

    #pragma unroll
    for (int mf = 0; mf < 4; mf++)
        #pragma unroll
        for (int nf = 0; nf < 4; nf++)
            #pragma unroll
            for (int t = 0; t < 4; t++) {
                int m = rowBase + wm + mf * 16 + gid + (t >> 1) * 8;
                int n = colBase + wn + nf * 8 + tg * 2 + (t & 1);
                Out[(size_t)m * DD + n] = acc[mf][nf][t] + bias[n];
            }
}

// scores: (q.k^T + qrel[rel]) / 8 with mask -> g_attn fp32
__global__ __launch_bounds__(256) void k_scores(const int* __restrict__ mask)
{
    extern __shared__ char sm[];
    const uint32_t sb = smem_cast(sm);
    const int tid = threadIdx.x, warp = tid >> 5, lane = tid & 31;
    const int gid = lane >> 2, tg = lane & 3;
    const int wm = (warp >> 2) * 64, wn = (warp & 3) * 32;
    const int bh = blockIdx.z;
    const int qt = blockIdx.y * 128, kt = blockIdx.x * 128;
    const __nv_bfloat16* gAh = s_qh + ((size_t)bh * LL + qt) * HSZ;
    const __nv_bfloat16* gAl = s_ql + ((size_t)bh * LL + qt) * HSZ;
    const __nv_bfloat16* gBh = s_kh + ((size_t)bh * LL + kt) * HSZ;
    const __nv_bfloat16* gBl = s_kl + ((size_t)bh * LL + kt) * HSZ;

    float acc[4][4][4];
    #pragma unroll
    for (int i = 0; i < 4; i++) for (int j = 0; j < 4; j++) for (int t = 0; t < 4; t++)
        acc[i][j][t] = 0.f;

    auto fill = [&](int c, int stg) {
        uint32_t aH = sb + stg * STG128, aL = aH + SZA, bH = aL + SZA, bL = bH + SZB128;
        fill_x3<128>(aH, aL, bH, bL, gAh, gAl, HSZ, gBh, gBl, HSZ, c * 32, c * 32, tid);
    };
    fill(0, 0); CP_COMMIT();
    fill(1, 1); CP_COMMIT();
    for (int c = 0; c < 2; c++) {
        CP_WAIT1(); __syncthreads();
        int stg = c & 1;
        uint32_t aH = sb + stg * STG128, aL = aH + SZA, bH = aL + SZA, bL = bH + SZB128;
        stage_mma<4>(acc, aH, aL, bH, bL, wm, wn, lane);
        __syncthreads();
    }
    CP_WAITALL();

    const int bb = bh >> 4;
    #pragma unroll
    for (int mf = 0; mf < 4; mf++)
        #pragma unroll
        for (int nf = 0; nf < 4; nf++)
            #pragma unroll
            for (int t = 0; t < 4; t++) {
                int qi = qt + wm + mf * 16 + gid + (t >> 1) * 8;
                int kj = kt + wn + nf * 8 + tg * 2 + (t & 1);
                int dd = kj - qi;
                int ridx = dd < -128 ? 0 : (dd > 128 ? 256 : dd + 128);
                float v = (acc[mf][nf][t] + g_qrel[((size_t)bh * LL + qi) * RR + ridx]) * 0.125f;
                if (mask[bb * LL + kj] == 0) v = -INFINITY;
                g_attn[((size_t)bh * LL + qi) * LL + kj] = v;
            }
}

// qrel: q . embd_k[r] -> g_qrel fp32
__global__ __launch_bounds__(256) void k_qrelK()
{
    extern __shared__ char sm[];
    const uint32_t sb = smem_cast(sm);
    const int tid = threadIdx.x, warp = tid >> 5, lane = tid & 31;
    const int gid = lane >> 2, tg = lane & 3;
    const int wm = (warp >> 2) * 64, wn = (warp & 3) * 32;
    const int bh = blockIdx.z;
    const int lt = blockIdx.y * 128, rt = blockIdx.x * 128;
    const __nv_bfloat16* gAh = s_qh + ((size_t)bh * LL + lt) * HSZ;
    const __nv_bfloat16* gAl = s_ql + ((size_t)bh * LL + lt) * HSZ;
    const __nv_bfloat16* gBh = s_ekh + (size_t)rt * HSZ;
    const __nv_bfloat16* gBl = s_ekl + (size_t)rt * HSZ;

    float acc[4][4][4];
    #pragma unroll
    for (int i = 0; i < 4; i++) for (int j = 0; j < 4; j++) for (int t = 0; t < 4; t++)
        acc[i][j][t] = 0.f;

    auto fill = [&](int c, int stg) {
        uint32_t aH = sb + stg * STG128, aL = aH + SZA, bH = aL + SZA, bL = bH + SZB128;
        fill_x3<128>(aH, aL, bH, bL, gAh, gAl, HSZ, gBh, gBl, HSZ, c * 32, c * 32, tid);
    };
    fill(0, 0); CP_COMMIT();
    fill(1, 1); CP_COMMIT();
    for (int c = 0; c < 2; c++) {
        CP_WAIT1(); __syncthreads();
        int stg = c & 1;
        uint32_t aH = sb + stg * STG128, aL = aH + SZA, bH = aL + SZA, bL = bH + SZB128;
        stage_mma<4>(acc, aH, aL, bH, bL, wm, wn, lane);
        __syncthreads();
    }
    CP_WAITALL();

    #pragma unroll
    for (int mf = 0; mf < 4; mf++)
        #pragma unroll
        for (int nf = 0; nf < 4; nf++)
            #pragma unroll
            for (int t = 0; t < 4; t++) {
                int l = lt + wm + mf * 16 + gid + (t >> 1) * 8;
                int r = rt + wn + nf * 8 + tg * 2 + (t & 1);
                if (r < RR)
                    g_qrel[((size_t)bh * LL + l) * RR + r] = acc[mf][nf][t];
            }
}

// softmax + bucket mass; emits probs hi/lo + w hi/lo (padded rows)
__global__ __launch_bounds__(256) void k_softmax2()
{
    int row = blockIdx.x;
    int q = row & 1023;
    const float* p = &g_attn[(size_t)row * LL];
    int tid = threadIdx.x, wid = tid >> 5, lane = tid & 31;
    __shared__ float red[8];
    __shared__ float ws[RR];

    float v[4];
    float mx = -INFINITY;
    #pragma unroll
    for (int s = 0; s < 4; s++) { v[s] = p[tid + (s << 8)]; mx = fmaxf(mx, v[s]); }
    #pragma unroll
    for (int o = 16; o; o >>= 1) mx = fmaxf(mx, __shfl_xor_sync(0xffffffffu, mx, o));
    if (lane == 0) red[wid] = mx;
    __syncthreads();
    mx = red[0];
    #pragma unroll
    for (int i = 1; i < 8; i++) mx = fmaxf(mx, red[i]);
    __syncthreads();

    float sum = 0.f;
    #pragma unroll
    for (int s = 0; s < 4; s++) { v[s] = __expf(v[s] - mx); sum += v[s]; }
    #pragma unroll
    for (int o = 16; o; o >>= 1) sum += __shfl_xor_sync(0xffffffffu, sum, o);
    if (lane == 0) red[wid] = sum;
    __syncthreads();
    sum = 0.f;
    #pragma unroll
    for (int i = 0; i < 8; i++) sum += red[i];
    float inv = 1.f / sum;

    ws[tid] = 0.f;
    if (tid == 0) ws[256] = 0.f;
    __syncthreads();

    float l0 = 0.f, l2 = 0.f;
    #pragma unroll
    for (int s = 0; s < 4; s++) {
        int k = tid + (s << 8);
        float pv = v[s] * inv;
        __nv_bfloat16 h2, lo2; bf_split(pv, h2, lo2);
        s_ph[(size_t)row * LL + k] = h2;
        s_pl[(size_t)row * LL + k] = lo2;
        int dd = k - q;
        if (dd <= -128)      l0 += pv;
        else if (dd >= 128)  l2 += pv;
        else                 ws[dd + 128] = pv;    // bijection per row
    }
    #pragma unroll
    for (int o = 16; o; o >>= 1) {
        l0 += __shfl_down_sync(0xffffffffu, l0, o);
        l2 += __shfl_down_sync(0xffffffffu, l2, o);
    }
    if (lane == 0) {
        if (l0 != 0.f) atomicAdd(&ws[0], l0);
        if (l2 != 0.f) atomicAdd(&ws[256], l2);
    }
    __syncthreads();

    {
        __nv_bfloat16 h2, lo2; bf_split(ws[tid], h2, lo2);
        s_wh[(size_t)row * RPAD + tid] = h2;
        s_wl[(size_t)row * RPAD + tid] = lo2;
    }
    if (tid < 32) {
        float x = (tid == 0) ? ws[256] : 0.f;
        __nv_bfloat16 h2, lo2; bf_split(x, h2, lo2);
        s_wh[(size_t)row * RPAD + 256 + tid] = h2;
        s_wl[(size_t)row * RPAD + 256 + tid] = lo2;
    }
}

// ctx: probs@v + w@embd_v -> ctx hi/lo (BM=128, BN=64)
__global__ __launch_bounds__(256) void k_ctx()
{
    extern __shared__ char sm[];
    const uint32_t sb = smem_cast(sm);
    const int tid = threadIdx.x, warp = tid >> 5, lane = tid & 31;
    const int gid = lane >> 2, tg = lane & 3;
    const int wm = (warp >> 1) * 32, wn = (warp & 1) * 32;
    const int bh = blockIdx.y;
    const int qt = blockIdx.x * 128;

    const __nv_bfloat16* pAh = s_ph + ((size_t)bh * LL + qt) * LL;
    const __nv_bfloat16* pAl = s_pl + ((size_t)bh * LL + qt) * LL;
    const __nv_bfloat16* pBh = s_vth + (size_t)bh * HSZ * LL;
    const __nv_bfloat16* pBl = s_vtl + (size_t)bh * HSZ * LL;
    const __nv_bfloat16* wAh = s_wh + ((size_t)bh * LL + qt) * RPAD;
    const __nv_bfloat16* wAl = s_wl + ((size_t)bh * LL + qt) * RPAD;

    float acc[2][4][4];
    #pragma unroll
    for (int i = 0; i < 2; i++) for (int j = 0; j < 4; j++) for (int t = 0; t < 4; t++)
        acc[i][j][t] = 0.f;

    auto fill = [&](int c, int stg) {
        uint32_t aH = sb + stg * STG64, aL = aH + SZA, bH = aL + SZA, bL = bH + SZB64;
        if (c < 32)
            fill_x3<64>(aH, aL, bH, bL, pAh, pAl, LL, pBh, pBl, LL, c * 32, c * 32, tid);
        else
            fill_x3<64>(aH, aL, bH, bL, wAh, wAl, RPAD, s_evh, s_evl, RPAD,
                        (c - 32) * 32, (c - 32) * 32, tid);
    };
    fill(0, 0); CP_COMMIT();
    fill(1, 1); CP_COMMIT();
    for (int c = 0; c < 41; c++) {
        CP_WAIT1(); __syncthreads();
        int stg = c & 1;
        uint32_t aH = sb + stg * STG64, aL = aH + SZA, bH = aL + SZA, bL = bH + SZB64;
        stage_mma<2>(acc, aH, aL, bH, bL, wm, wn, lane);
        __syncthreads();
        if (c + 2 < 41) fill(c + 2, stg);
        CP_COMMIT();
    }
    CP_WAITALL();

    const int bb = bh >> 4, hh = bh & 15;
    #pragma unroll
    for (int mf = 0; mf < 2; mf++)
        #pragma unroll
        for (int nf = 0; nf < 4; nf++)
            #pragma unroll
            for (int t = 0; t < 4; t++) {
                int l = qt + wm + mf * 16 + gid + (t >> 1) * 8;
                int n = wn + nf * 8 + tg * 2 + (t & 1);
                __nv_bfloat16 h2, l2; bf_split(acc[mf][nf][t], h2, l2);
                size_t d = ((size_t)(bb * LL + l)) * DD + hh * HSZ + n;
                s_ch[d] = h2; s_cl[d] = l2;
            }
}

// ---------------- launch --------------------------------------------------------
extern "C" void kernel_launch(void* const* d_in, const int* in_sizes, int n_in,
                              void* d_out, int out_size)
{
    const float* x      = (const float*)d_in[0];
    const float* W_kqv  = (const float*)d_in[1];
    const float* b_kqv  = (const float*)d_in[2];
    const float* W_o    = (const float*)d_in[3];
    const float* b_o    = (const float*)d_in[4];
    const float* embd_k = (const float*)d_in[5];
    const float* embd_v = (const float*)d_in[6];
    const int*   mask   = (const int*)d_in[7];
    float* out = (float*)d_out;

    // unconditional (no static guards): host-side, capture-safe, idempotent
    cudaFuncSetAttribute(k_kqv,    cudaFuncAttributeMaxDynamicSharedMemorySize, 2 * STG128);
    cudaFuncSetAttribute(k_out,    cudaFuncAttributeMaxDynamicSharedMemorySize, 2 * STG128);
    cudaFuncSetAttribute(k_scores, cudaFuncAttributeMaxDynamicSharedMemorySize, 2 * STG128);
    cudaFuncSetAttribute(k_qrelK,  cudaFuncAttributeMaxDynamicSharedMemorySize, 2 * STG128);
    cudaFuncSetAttribute(k_ctx,    cudaFuncAttributeMaxDynamicSharedMemorySize, 2 * STG64);

    // conversions
    cvt_x<<<8192, 256>>>(x);
    cvt_wT<<<dim3(96, 32), 256>>>(W_kqv, 3072);
    cvt_wT<<<dim3(32, 32), 256>>>(W_o, 1024);
    cvt_ek<<<96, 256>>>(embd_k);
    cvt_ev<<<72, 256>>>(embd_v);
    // pipeline
    k_kqv<<<dim3(24, 64), 256, 2 * STG128>>>(b_kqv);
    k_qrelK<<<dim3(3, 8, NBH), 256, 2 * STG128>>>();
    k_scores<<<dim3(8, 8, NBH), 256, 2 * STG128>>>(mask);
    k_softmax2<<<NBH * LL, 256>>>();
    k_ctx<<<dim3(8, NBH), 256, 2 * STG64>>>();
    k_out<<<dim3(8, 64), 256, 2 * STG128>>>(b_o, out);
}